// round 10
// baseline (speedup 1.0000x reference)
#include <cuda_runtime.h>
#include <cuda_bf16.h>
#include <cstdint>
#include <math.h>

// Problem constants (fixed by reference)
#define BB 2
#define LL 2048
#define DM 1024
#define DI 2048
#define DS 16
#define DR 64
#define NR (BB*LL)     // 4096 rows (b,l)
#define XZW (2*DI)     // 4096
#define XD  96         // dt_rank + 2*d_state
#define NCH 4
#define LC (LL/NCH)    // 512

// Scratch (device globals; no allocation allowed)
__device__ float g_xz  [(size_t)NR*XZW];   // in_proj output [B,L,2*DI]
__device__ float g_xpt [(size_t)BB*DI*LL]; // conv+silu output transposed [B,DI,L]
__device__ float g_xdbl[(size_t)NR*XD];    // x_proj output [B,L,96]
__device__ float g_dtt [(size_t)BB*DI*LL]; // softplus(delta) transposed [B,DI,L]
__device__ float g_yt  [(size_t)BB*DI*LL]; // scan output (+D*x) [B,DI,L]
__device__ float g_xpart[(size_t)8*NR*128];// xproj split-K partials [8][4096][128]
__device__ float g_delta[(size_t)NR*DI];   // raw delta GEMM output [B,L,DI]
__device__ float g_q   [(size_t)3*BB*DI*DS]; // pass1 final states [chunk][ch][16]
__device__ float g_sdt [(size_t)3*BB*DI];    // pass1 per-chunk sum(dt) [chunk][ch]

// bf16 split buffers for tensor-core GEMMs
__device__ __nv_bfloat16 g_xhi [(size_t)NR*DM];
__device__ __nv_bfloat16 g_xlo [(size_t)NR*DM];
__device__ __nv_bfloat16 g_w1hi[(size_t)XZW*DM];
__device__ __nv_bfloat16 g_w1lo[(size_t)XZW*DM];
__device__ __nv_bfloat16 g_xphi[(size_t)NR*DI];   // conv+silu output hi
__device__ __nv_bfloat16 g_xplo[(size_t)NR*DI];   // conv+silu output lo
__device__ __nv_bfloat16 g_w3hi[(size_t)128*DI];  // x_proj_w padded to 128 rows
__device__ __nv_bfloat16 g_w3lo[(size_t)128*DI];
__device__ __nv_bfloat16 g_dthi[(size_t)NR*DR];   // x_dbl[:, :64] hi (delta A)
__device__ __nv_bfloat16 g_dtlo[(size_t)NR*DR];
__device__ __nv_bfloat16 g_wdhi[(size_t)DI*DR];   // dt_proj_w hi/lo
__device__ __nv_bfloat16 g_wdlo[(size_t)DI*DR];
__device__ __nv_bfloat16 g_ghi [(size_t)NR*DI];
__device__ __nv_bfloat16 g_glo [(size_t)NR*DI];
__device__ __nv_bfloat16 g_w2hi[(size_t)DM*DI];
__device__ __nv_bfloat16 g_w2lo[(size_t)DM*DI];

__device__ __forceinline__ float siluf(float x) { return x / (1.0f + __expf(-x)); }
__device__ __forceinline__ float softplusf(float x) {
    return (x > 20.0f) ? x : log1pf(__expf(x));
}

// ===========================================================================
// Base-target (sm_103, no 'a') tensor path: ldmatrix + mma.sync + cp.async
// ===========================================================================
__device__ __forceinline__ uint32_t smem_u32(const void* p) {
    uint32_t a;
    asm("{ .reg .u64 t; cvta.to.shared.u64 t, %1; cvt.u32.u64 %0, t; }" : "=r"(a) : "l"(p));
    return a;
}
__device__ __forceinline__ void cpa16(uint32_t dst, const void* src) {
    asm volatile("cp.async.cg.shared.global [%0], [%1], 16;" :: "r"(dst), "l"(src));
}
__device__ __forceinline__ void ldsm4(uint32_t* r, uint32_t a) {
    asm volatile("ldmatrix.sync.aligned.m8n8.x4.shared.b16 {%0,%1,%2,%3}, [%4];"
                 : "=r"(r[0]), "=r"(r[1]), "=r"(r[2]), "=r"(r[3]) : "r"(a));
}
__device__ __forceinline__ void mma16816(float* c, const uint32_t* a, const uint32_t* b) {
    asm volatile("mma.sync.aligned.m16n8k16.row.col.f32.bf16.bf16.f32 "
                 "{%0,%1,%2,%3}, {%4,%5,%6,%7}, {%8,%9}, {%0,%1,%2,%3};"
                 : "+f"(c[0]), "+f"(c[1]), "+f"(c[2]), "+f"(c[3])
                 : "r"(a[0]), "r"(a[1]), "r"(a[2]), "r"(a[3]), "r"(b[0]), "r"(b[1]));
}

// ===========================================================================
// Split fp32 -> bf16 hi + bf16 lo (residual)
// ===========================================================================
__global__ void split_bf16(const float* __restrict__ in, __nv_bfloat16* __restrict__ hi,
                           __nv_bfloat16* __restrict__ lo, int n4)
{
    int i = blockIdx.x * blockDim.x + threadIdx.x;
    if (i >= n4) return;
    float4 v = *(const float4*)(in + (size_t)i * 4);
    __nv_bfloat16 h0 = __float2bfloat16(v.x), h1 = __float2bfloat16(v.y);
    __nv_bfloat16 h2 = __float2bfloat16(v.z), h3 = __float2bfloat16(v.w);
    __nv_bfloat16 l0 = __float2bfloat16(v.x - __bfloat162float(h0));
    __nv_bfloat16 l1 = __float2bfloat16(v.y - __bfloat162float(h1));
    __nv_bfloat16 l2 = __float2bfloat16(v.z - __bfloat162float(h2));
    __nv_bfloat16 l3 = __float2bfloat16(v.w - __bfloat162float(h3));
    __nv_bfloat162* hp = (__nv_bfloat162*)(hi + (size_t)i * 4);
    __nv_bfloat162* lp = (__nv_bfloat162*)(lo + (size_t)i * 4);
    hp[0] = __nv_bfloat162(h0, h1); hp[1] = __nv_bfloat162(h2, h3);
    lp[0] = __nv_bfloat162(l0, l1); lp[1] = __nv_bfloat162(l2, l3);
}

// Split + zero-pad x_proj_w [96,2048] -> [128,2048] bf16 hi/lo
__global__ void split_pad_xw(const float* __restrict__ xw)
{
    int i = blockIdx.x * blockDim.x + threadIdx.x;   // float4 index over [128][2048]
    if (i >= 128 * DI / 4) return;
    int row = i >> 9;                                // 512 float4 per row
    float4 v = make_float4(0.f, 0.f, 0.f, 0.f);
    if (row < 96) v = *(const float4*)(xw + (size_t)i * 4);
    __nv_bfloat16 h0 = __float2bfloat16(v.x), h1 = __float2bfloat16(v.y);
    __nv_bfloat16 h2 = __float2bfloat16(v.z), h3 = __float2bfloat16(v.w);
    __nv_bfloat162* hp = (__nv_bfloat162*)(g_w3hi + (size_t)i * 4);
    __nv_bfloat162* lp = (__nv_bfloat162*)(g_w3lo + (size_t)i * 4);
    hp[0] = __nv_bfloat162(h0, h1); hp[1] = __nv_bfloat162(h2, h3);
    lp[0] = __nv_bfloat162(__float2bfloat16(v.x - __bfloat162float(h0)),
                           __float2bfloat16(v.y - __bfloat162float(h1)));
    lp[1] = __nv_bfloat162(__float2bfloat16(v.z - __bfloat162float(h2)),
                           __float2bfloat16(v.w - __bfloat162float(h3)));
}

// ===========================================================================
// Split-bf16 HMMA GEMM v4: C[M,N] = A[M,K] @ B[N,K]^T, fp32 accumulate.
// CTA tile 128x128, warp tile 64x32 (8 warps, 2x4), stage K=16.
// 4-stage cp.async ring, one barrier/stage, pitch-48 smem, 2 CTAs/SM.
// v4: bank-conflict-free cp.async write mapping (each 8-lane phase covers
// all 32 banks once; chunk start-bank = (12*row + 4*half) mod 32).
// Split-K via blockIdx.z (kChunk columns each, partial written at z*cStride).
// ===========================================================================
#define PITCH 48
#define OA_HI 0
#define OA_LO 6144         // +128*48
#define OB_HI 12288
#define OB_LO 18432        // +128*48
#define STG   24576
#define NSTG  4
#define HM_SMEM (NSTG*STG) // 98304 per CTA -> 2 CTAs/SM

__global__ void __launch_bounds__(256, 2)
hmma_gemm(const __nv_bfloat16* __restrict__ Ahi, const __nv_bfloat16* __restrict__ Alo,
          const __nv_bfloat16* __restrict__ Bhi, const __nv_bfloat16* __restrict__ Blo,
          float* __restrict__ C, int N, int K, int kChunk, size_t cStride)
{
    extern __shared__ char sm_[];
    const uint32_t sb = smem_u32(sm_);
    const int tid = threadIdx.x, lane = tid & 31, wid = tid >> 5;
    const int wm = wid >> 2, wn = wid & 3;
    const int m0 = blockIdx.y * 128, n0 = blockIdx.x * 128;
    const int kOffB = blockIdx.z * kChunk * 2;      // byte offset along K
    C += (size_t)blockIdx.z * cStride;
    const int nst = kChunk >> 4;

    float acc[4][4][4];
    #pragma unroll
    for (int i = 0; i < 4; ++i)
        #pragma unroll
        for (int j = 0; j < 4; ++j)
            #pragma unroll
            for (int q = 0; q < 4; ++q) acc[i][j][q] = 0.0f;

    // conflict-free write mapping:
    //   lanes 0-7  -> rows 0-7  half 0 ; lanes 8-15  -> rows 0-7  half 1
    //   lanes 16-23-> rows 8-15 half 0 ; lanes 24-31 -> rows 8-15 half 1
    const int lr = wid * 16 + (lane & 7) + ((lane >> 4) << 3);
    const int lh = ((lane >> 3) & 1) * 16;
    const uint32_t so = (uint32_t)(lr * PITCH + lh);
    const char* pAh = (const char*)(Ahi + (size_t)(m0 + lr) * K) + kOffB + lh;
    const char* pAl = (const char*)(Alo + (size_t)(m0 + lr) * K) + kOffB + lh;
    const char* pBh = (const char*)(Bhi + (size_t)(n0 + lr) * K) + kOffB + lh;
    const char* pBl = (const char*)(Blo + (size_t)(n0 + lr) * K) + kOffB + lh;

    auto load_stage = [&](int s) {
        const uint32_t st = sb + (s & (NSTG-1)) * STG;
        const int kb = s * 32;
        cpa16(st + OA_HI + so, pAh + kb);
        cpa16(st + OA_LO + so, pAl + kb);
        cpa16(st + OB_HI + so, pBh + kb);
        cpa16(st + OB_LO + so, pBl + kb);
        asm volatile("cp.async.commit_group;");
    };

    load_stage(0);
    load_stage(1);
    load_stage(2);

    const uint32_t aOff = (uint32_t)((wm*64 + (lane & 15)) * PITCH + (lane >> 4) * 16);
    const uint32_t bOff = (uint32_t)((wn*32 + (lane & 7) + ((lane >> 4) * 8)) * PITCH
                                     + ((lane >> 3) & 1) * 16);

    for (int s = 0; s < nst; ++s) {
        asm volatile("cp.async.wait_group 2;");
        __syncthreads();
        if (s + 3 < nst) load_stage(s + 3);
        else asm volatile("cp.async.commit_group;");

        const uint32_t st = sb + (s & (NSTG-1)) * STG;
        const uint32_t aB = st + aOff;
        const uint32_t bB = st + OB_HI + bOff;

        uint32_t ah[4][4], bh[2][4];
        #pragma unroll
        for (int i = 0; i < 4; ++i) ldsm4(ah[i], aB + i * 16*PITCH);
        ldsm4(bh[0], bB);
        ldsm4(bh[1], bB + 16*PITCH);
        #pragma unroll
        for (int i = 0; i < 4; ++i)
            #pragma unroll
            for (int j = 0; j < 4; ++j)
                mma16816(acc[i][j], ah[i], &bh[j >> 1][(j & 1) * 2]);

        uint32_t al[4][4];
        #pragma unroll
        for (int i = 0; i < 4; ++i) ldsm4(al[i], aB + OA_LO + i * 16*PITCH);
        #pragma unroll
        for (int i = 0; i < 4; ++i)
            #pragma unroll
            for (int j = 0; j < 4; ++j)
                mma16816(acc[i][j], al[i], &bh[j >> 1][(j & 1) * 2]);

        uint32_t bl[2][4];
        ldsm4(bl[0], bB + (OB_LO - OB_HI));
        ldsm4(bl[1], bB + (OB_LO - OB_HI) + 16*PITCH);
        #pragma unroll
        for (int i = 0; i < 4; ++i)
            #pragma unroll
            for (int j = 0; j < 4; ++j)
                mma16816(acc[i][j], ah[i], &bl[j >> 1][(j & 1) * 2]);
    }

    // epilogue: fp32 direct to global
    #pragma unroll
    for (int i = 0; i < 4; ++i)
        #pragma unroll
        for (int j = 0; j < 4; ++j) {
            int row = m0 + wm*64 + i*16 + (lane >> 2);
            int col = n0 + wn*32 + j*8 + (lane & 3)*2;
            *(float2*)(C + (size_t)row * N + col) =
                make_float2(acc[i][j][0], acc[i][j][1]);
            *(float2*)(C + (size_t)(row + 8) * N + col) =
                make_float2(acc[i][j][2], acc[i][j][3]);
        }
}

// Reduce xproj split-K partials: g_xdbl[m][c] = sum_z g_xpart[z][m][c], c<96.
// Also emits bf16 hi/lo of cols 0..63 (delta GEMM A operand).
__global__ void reduce_xdbl()
{
    int idx = blockIdx.x * blockDim.x + threadIdx.x;   // 0 .. 4096*24-1
    if (idx >= NR * 24) return;
    int m = idx / 24, c = (idx % 24) * 4;
    const float* p = g_xpart + (size_t)m * 128 + c;
    float4 s = make_float4(0.f, 0.f, 0.f, 0.f);
    #pragma unroll
    for (int z = 0; z < 8; ++z) {
        float4 v = *(const float4*)(p + (size_t)z * NR * 128);
        s.x += v.x; s.y += v.y; s.z += v.z; s.w += v.w;
    }
    *(float4*)(g_xdbl + (size_t)m * XD + c) = s;
    if (c < DR) {
        __nv_bfloat16 h0 = __float2bfloat16(s.x), h1 = __float2bfloat16(s.y);
        __nv_bfloat16 h2 = __float2bfloat16(s.z), h3 = __float2bfloat16(s.w);
        __nv_bfloat162* hp = (__nv_bfloat162*)(g_dthi + (size_t)m * DR + c);
        __nv_bfloat162* lp = (__nv_bfloat162*)(g_dtlo + (size_t)m * DR + c);
        hp[0] = __nv_bfloat162(h0, h1); hp[1] = __nv_bfloat162(h2, h3);
        lp[0] = __nv_bfloat162(__float2bfloat16(s.x - __bfloat162float(h0)),
                               __float2bfloat16(s.y - __bfloat162float(h1)));
        lp[1] = __nv_bfloat162(__float2bfloat16(s.z - __bfloat162float(h2)),
                               __float2bfloat16(s.w - __bfloat162float(h3)));
    }
}

// ---------------------------------------------------------------------------
// Causal depthwise conv (width 4) + bias + silu over xz[:, :, 0:DI].
// Writes bf16 hi/lo [B,L,DI] (for xproj HMMA) and fp32 transposed [B,DI,L].
// ---------------------------------------------------------------------------
__global__ void conv_silu_kernel(const float* __restrict__ conv_w,
                                 const float* __restrict__ conv_b)
{
    __shared__ float sIn[35][33];
    __shared__ float sOut[32][33];
    const int b = blockIdx.z, d0 = blockIdx.y * 32, l0 = blockIdx.x * 32;
    const int tid = threadIdx.x, tx = tid & 31, ty = tid >> 5;

    for (int r = ty; r < 35; r += 8) {
        int gl = l0 + r - 3;
        sIn[r][tx] = (gl >= 0) ? g_xz[(size_t)(b*LL + gl) * XZW + d0 + tx] : 0.0f;
    }
    __syncthreads();

    float4 w = *(const float4*)(conv_w + (d0 + tx) * 4);
    float cb = conv_b[d0 + tx];
    #pragma unroll
    for (int i = 0; i < 4; ++i) {
        int r = ty + i * 8;
        float v = sIn[r][tx]*w.x + sIn[r+1][tx]*w.y + sIn[r+2][tx]*w.z + sIn[r+3][tx]*w.w + cb;
        v = siluf(v);
        sOut[r][tx] = v;
        size_t idx = (size_t)(b*LL + l0 + r) * DI + d0 + tx;
        __nv_bfloat16 h = __float2bfloat16(v);
        g_xphi[idx] = h;
        g_xplo[idx] = __float2bfloat16(v - __bfloat162float(h));
    }
    __syncthreads();
    #pragma unroll
    for (int i = 0; i < 4; ++i) {
        int dd = ty + i * 8;
        g_xpt[(size_t)(b*DI + d0 + dd) * LL + l0 + tx] = sOut[tx][dd];
    }
}

// ---------------------------------------------------------------------------
// delta transpose + bias + softplus:
// g_dtt[(b*DI+n)*LL + l] = softplus(g_delta[(b*LL+l)*DI + n] + dtb[n])
// ---------------------------------------------------------------------------
__global__ void dtrans_kernel(const float* __restrict__ dtb)
{
    __shared__ float sD[32][33];
    const int b = blockIdx.z, n0 = blockIdx.y * 32, l0 = blockIdx.x * 32;
    const int tid = threadIdx.x, tx = tid & 31, ty = tid >> 5;

    #pragma unroll
    for (int i = 0; i < 4; ++i) {
        int r = ty + i * 8;   // local l
        sD[r][tx] = g_delta[(size_t)(b*LL + l0 + r) * DI + n0 + tx];
    }
    __syncthreads();
    #pragma unroll
    for (int i = 0; i < 4; ++i) {
        int ny = ty + i * 8;  // local n
        int n = n0 + ny;
        float v = softplusf(sD[tx][ny] + dtb[n]);
        g_dtt[(size_t)(b*DI + n) * LL + l0 + tx] = v;
    }
}

// ---------------------------------------------------------------------------
// Chunked selective scan, pass 1: per-chunk final state q_c and sum(dt).
// ---------------------------------------------------------------------------
__global__ __launch_bounds__(256)
void scan_pass1(const float* __restrict__ A_log)
{
    const int tid = threadIdx.x;
    const int ch = blockIdx.x * 32 + (tid >> 3);
    const int g  = tid & 7;
    const int c  = blockIdx.y;            // 0..2
    const int d  = ch & (DI - 1);
    const int b  = ch >> 11;
    const int n0 = g * 2;

    const float A0 = -__expf(A_log[d*DS + n0]);
    const float A1 = -__expf(A_log[d*DS + n0 + 1]);

    const float* __restrict__ dtp = g_dtt + (size_t)ch * LL + c * LC;
    const float* __restrict__ xpp = g_xpt + (size_t)ch * LL + c * LC;
    const float* __restrict__ rp  = g_xdbl + (size_t)(b*LL + c*LC) * XD + DR + n0;

    float h0 = 0.f, h1 = 0.f, sdt = 0.f;
    float dt[2][4], xv[2][4];
    float2 Bv[2][4];

    #pragma unroll
    for (int u = 0; u < 4; ++u) {
        dt[0][u] = __ldg(dtp + u);
        xv[0][u] = __ldg(xpp + u);
        Bv[0][u] = *(const float2*)(rp + (size_t)u * XD);
    }

    for (int l = 0; l < LC; l += 8) {
        #pragma unroll
        for (int u = 0; u < 4; ++u) {
            int ll = l + 4 + u;
            dt[1][u] = __ldg(dtp + ll);
            xv[1][u] = __ldg(xpp + ll);
            Bv[1][u] = *(const float2*)(rp + (size_t)ll * XD);
        }
        #pragma unroll
        for (int u = 0; u < 4; ++u) {
            float dtx = dt[0][u] * xv[0][u];
            h0 = fmaf(__expf(dt[0][u] * A0), h0, dtx * Bv[0][u].x);
            h1 = fmaf(__expf(dt[0][u] * A1), h1, dtx * Bv[0][u].y);
            sdt += dt[0][u];
        }
        int lp = (l + 8 < LC) ? l + 8 : 0;    // clamped prefetch (last unused)
        #pragma unroll
        for (int u = 0; u < 4; ++u) {
            int ll = lp + u;
            dt[0][u] = __ldg(dtp + ll);
            xv[0][u] = __ldg(xpp + ll);
            Bv[0][u] = *(const float2*)(rp + (size_t)ll * XD);
        }
        #pragma unroll
        for (int u = 0; u < 4; ++u) {
            float dtx = dt[1][u] * xv[1][u];
            h0 = fmaf(__expf(dt[1][u] * A0), h0, dtx * Bv[1][u].x);
            h1 = fmaf(__expf(dt[1][u] * A1), h1, dtx * Bv[1][u].y);
            sdt += dt[1][u];
        }
    }

    float* qp = g_q + ((size_t)c * (BB*DI) + ch) * DS + n0;
    qp[0] = h0; qp[1] = h1;
    if (g == 0) g_sdt[(size_t)c * (BB*DI) + ch] = sdt;
}

// ---------------------------------------------------------------------------
// Chunked selective scan, pass 2: carry-in from pass1, full y output.
// ---------------------------------------------------------------------------
__global__ __launch_bounds__(256)
void scan_pass2(const float* __restrict__ A_log, const float* __restrict__ Dv)
{
    const int tid = threadIdx.x;
    const int ch = blockIdx.x * 32 + (tid >> 3);
    const int g  = tid & 7;
    const int c  = blockIdx.y;            // 0..3
    const int d  = ch & (DI - 1);
    const int b  = ch >> 11;
    const int n0 = g * 2;

    const float A0 = -__expf(A_log[d*DS + n0]);
    const float A1 = -__expf(A_log[d*DS + n0 + 1]);
    const float Dd = Dv[d];

    float h0 = 0.f, h1 = 0.f;
    for (int j = 0; j < c; ++j) {
        float s = __ldg(g_sdt + (size_t)j * (BB*DI) + ch);
        const float* qp = g_q + ((size_t)j * (BB*DI) + ch) * DS + n0;
        h0 = fmaf(__expf(s * A0), h0, __ldg(qp));
        h1 = fmaf(__expf(s * A1), h1, __ldg(qp + 1));
    }

    const float* __restrict__ dtp = g_dtt + (size_t)ch * LL + c * LC;
    const float* __restrict__ xpp = g_xpt + (size_t)ch * LL + c * LC;
    const float* __restrict__ rp  = g_xdbl + (size_t)(b*LL + c*LC) * XD + DR + n0;
    float* __restrict__ yp = g_yt + (size_t)ch * LL + c * LC;

    float dt[2][4], xv[2][4];
    float2 Bv[2][4], Cv[2][4];

    #pragma unroll
    for (int u = 0; u < 4; ++u) {
        dt[0][u] = __ldg(dtp + u);
        xv[0][u] = __ldg(xpp + u);
        Bv[0][u] = *(const float2*)(rp + (size_t)u * XD);
        Cv[0][u] = *(const float2*)(rp + (size_t)u * XD + DS);
    }

    for (int l = 0; l < LC; l += 8) {
        #pragma unroll
        for (int u = 0; u < 4; ++u) {
            int ll = l + 4 + u;
            dt[1][u] = __ldg(dtp + ll);
            xv[1][u] = __ldg(xpp + ll);
            Bv[1][u] = *(const float2*)(rp + (size_t)ll * XD);
            Cv[1][u] = *(const float2*)(rp + (size_t)ll * XD + DS);
        }
        #pragma unroll
        for (int u = 0; u < 4; ++u) {
            float dtx = dt[0][u] * xv[0][u];
            h0 = fmaf(__expf(dt[0][u] * A0), h0, dtx * Bv[0][u].x);
            h1 = fmaf(__expf(dt[0][u] * A1), h1, dtx * Bv[0][u].y);
            float y = fmaf(h0, Cv[0][u].x, h1 * Cv[0][u].y);
            y += __shfl_down_sync(0xffffffffu, y, 4, 8);
            y += __shfl_down_sync(0xffffffffu, y, 2, 8);
            y += __shfl_down_sync(0xffffffffu, y, 1, 8);
            if (g == 0) yp[l + u] = fmaf(Dd, xv[0][u], y);
        }
        int lp = (l + 8 < LC) ? l + 8 : 0;
        #pragma unroll
        for (int u = 0; u < 4; ++u) {
            int ll = lp + u;
            dt[0][u] = __ldg(dtp + ll);
            xv[0][u] = __ldg(xpp + ll);
            Bv[0][u] = *(const float2*)(rp + (size_t)ll * XD);
            Cv[0][u] = *(const float2*)(rp + (size_t)ll * XD + DS);
        }
        #pragma unroll
        for (int u = 0; u < 4; ++u) {
            float dtx = dt[1][u] * xv[1][u];
            h0 = fmaf(__expf(dt[1][u] * A0), h0, dtx * Bv[1][u].x);
            h1 = fmaf(__expf(dt[1][u] * A1), h1, dtx * Bv[1][u].y);
            float y = fmaf(h0, Cv[1][u].x, h1 * Cv[1][u].y);
            y += __shfl_down_sync(0xffffffffu, y, 4, 8);
            y += __shfl_down_sync(0xffffffffu, y, 2, 8);
            y += __shfl_down_sync(0xffffffffu, y, 1, 8);
            if (g == 0) yp[l + 4 + u] = fmaf(Dd, xv[1][u], y);
        }
    }
}

// ---------------------------------------------------------------------------
// g = y_t * silu(z), fused with bf16 hi/lo split (feeds out_proj HMMA)
// ---------------------------------------------------------------------------
__global__ void gmul_split_kernel()
{
    __shared__ float sY[32][33];
    const int b = blockIdx.z, d0 = blockIdx.y * 32, l0 = blockIdx.x * 32;
    const int tid = threadIdx.x, tx = tid & 31, ty = tid >> 5;

    #pragma unroll
    for (int i = 0; i < 4; ++i) {
        int dd = ty + i * 8;
        sY[dd][tx] = g_yt[(size_t)(b*DI + d0 + dd) * LL + l0 + tx];
    }
    __syncthreads();
    #pragma unroll
    for (int i = 0; i < 4; ++i) {
        int r = ty + i * 8;
        size_t idx = (size_t)(b*LL + l0 + r) * DI + d0 + tx;
        float z = g_xz[(size_t)(b*LL + l0 + r) * XZW + DI + d0 + tx];
        float v = sY[tx][r] * siluf(z);
        __nv_bfloat16 h = __float2bfloat16(v);
        g_ghi[idx] = h;
        g_glo[idx] = __float2bfloat16(v - __bfloat162float(h));
    }
}

// ---------------------------------------------------------------------------
extern "C" void kernel_launch(void* const* d_in, const int* in_sizes, int n_in,
                              void* d_out, int out_size)
{
    const float* x       = (const float*)d_in[0];
    const float* in_proj = (const float*)d_in[1];
    const float* conv_w  = (const float*)d_in[2];
    const float* conv_b  = (const float*)d_in[3];
    const float* x_proj  = (const float*)d_in[4];
    const float* dt_w    = (const float*)d_in[5];
    const float* dt_b    = (const float*)d_in[6];
    const float* A_log   = (const float*)d_in[7];
    const float* Dv      = (const float*)d_in[8];
    const float* out_w   = (const float*)d_in[9];
    float* out = (float*)d_out;

    float *xz, *xpart, *delta;
    __nv_bfloat16 *xhi, *xlo, *w1hi, *w1lo, *xphi, *xplo, *w3hi, *w3lo;
    __nv_bfloat16 *dthi, *dtlo, *wdhi, *wdlo, *ghi, *glo, *w2hi, *w2lo;
    cudaGetSymbolAddress((void**)&xz,    g_xz);
    cudaGetSymbolAddress((void**)&xpart, g_xpart);
    cudaGetSymbolAddress((void**)&delta, g_delta);
    cudaGetSymbolAddress((void**)&xhi,   g_xhi);
    cudaGetSymbolAddress((void**)&xlo,   g_xlo);
    cudaGetSymbolAddress((void**)&w1hi,  g_w1hi);
    cudaGetSymbolAddress((void**)&w1lo,  g_w1lo);
    cudaGetSymbolAddress((void**)&xphi,  g_xphi);
    cudaGetSymbolAddress((void**)&xplo,  g_xplo);
    cudaGetSymbolAddress((void**)&w3hi,  g_w3hi);
    cudaGetSymbolAddress((void**)&w3lo,  g_w3lo);
    cudaGetSymbolAddress((void**)&dthi,  g_dthi);
    cudaGetSymbolAddress((void**)&dtlo,  g_dtlo);
    cudaGetSymbolAddress((void**)&wdhi,  g_wdhi);
    cudaGetSymbolAddress((void**)&wdlo,  g_wdlo);
    cudaGetSymbolAddress((void**)&ghi,   g_ghi);
    cudaGetSymbolAddress((void**)&glo,   g_glo);
    cudaGetSymbolAddress((void**)&w2hi,  g_w2hi);
    cudaGetSymbolAddress((void**)&w2lo,  g_w2lo);

    cudaFuncSetAttribute(hmma_gemm, cudaFuncAttributeMaxDynamicSharedMemorySize, HM_SMEM);

    // 0-2) splits (so in_proj hmma sits at launch index 3 for ncu)
    split_bf16<<<(NR*DM/4 + 255)/256, 256>>>(x, xhi, xlo, NR*DM/4);
    split_bf16<<<(XZW*DM/4 + 255)/256, 256>>>(in_proj, w1hi, w1lo, XZW*DM/4);
    split_bf16<<<(DM*DI/4 + 255)/256, 256>>>(out_w, w2hi, w2lo, DM*DI/4);
    // 3) xz = x @ in_proj_w^T  -> [4096, 4096]
    hmma_gemm<<<dim3(XZW/128, NR/128, 1), 256, HM_SMEM>>>(
        xhi, xlo, w1hi, w1lo, xz, XZW, DM, DM, 0);
    // 4) conv + silu (writes bf16 hi/lo + fp32 transposed)
    conv_silu_kernel<<<dim3(LL/32, DI/32, BB), 256>>>(conv_w, conv_b);
    // 5) pad+split x_proj_w; split dt_proj_w
    split_pad_xw<<<(128*DI/4 + 255)/256, 256>>>(x_proj);
    split_bf16<<<(DI*DR/4 + 255)/256, 256>>>(dt_w, wdhi, wdlo, DI*DR/4);
    // 6) x_dbl partials = x_p @ x_proj_w^T (split-K over 8 chunks of 256)
    hmma_gemm<<<dim3(1, NR/128, 8), 256, HM_SMEM>>>(
        xphi, xplo, w3hi, w3lo, xpart, 128, DI, DI/8, (size_t)NR*128);
    // 7) reduce partials -> g_xdbl; also bf16-split delta cols
    reduce_xdbl<<<(NR*24 + 255)/256, 256>>>();
    // 8) delta raw = x_dbl[:, :64] @ dt_proj_w^T (HMMA) -> [4096, 2048]
    hmma_gemm<<<dim3(DI/128, NR/128, 1), 256, HM_SMEM>>>(
        dthi, dtlo, wdhi, wdlo, delta, DI, DR, DR, 0);
    // 9) softplus(delta + bias), transposed to [B,DI,L]
    dtrans_kernel<<<dim3(LL/32, DI/32, BB), 256>>>(dt_b);
    // 10) chunked selective scan (2 passes)
    scan_pass1<<<dim3((BB*DI)/32, NCH-1), 256>>>(A_log);
    scan_pass2<<<dim3((BB*DI)/32, NCH), 256>>>(A_log, Dv);
    // 11) g = y * silu(z) fused with bf16 split
    gmul_split_kernel<<<dim3(LL/32, DI/32, BB), 256>>>();
    // 12) out = g @ out_proj_w^T
    hmma_gemm<<<dim3(DM/128, NR/128, 1), 256, HM_SMEM>>>(
        ghi, glo, w2hi, w2lo, out, DM, DI, DI, 0);
}

// round 11
// speedup vs baseline: 1.0437x; 1.0437x over previous
#include <cuda_runtime.h>
#include <cuda_bf16.h>
#include <cstdint>
#include <math.h>

// Problem constants (fixed by reference)
#define BB 2
#define LL 2048
#define DM 1024
#define DI 2048
#define DS 16
#define DR 64
#define NR (BB*LL)     // 4096 rows (b,l)
#define XZW (2*DI)     // 4096
#define XD  96         // dt_rank + 2*d_state
#define NCH 4
#define LC (LL/NCH)    // 512

// Scratch (device globals; no allocation allowed)
__device__ float g_xz  [(size_t)NR*XZW];   // in_proj output [B,L,2*DI]
__device__ float g_xpt [(size_t)BB*DI*LL]; // conv+silu output transposed [B,DI,L]
__device__ float g_xdbl[(size_t)NR*XD];    // x_proj output [B,L,96]
__device__ float g_dtt [(size_t)BB*DI*LL]; // softplus(delta) transposed [B,DI,L]
__device__ float g_yt  [(size_t)BB*DI*LL]; // scan output (+D*x) [B,DI,L]
__device__ float g_xpart[(size_t)8*NR*128];// xproj split-K partials [8][4096][128]
__device__ float g_delta[(size_t)NR*DI];   // raw delta GEMM output [B,L,DI]
__device__ float g_q   [(size_t)3*BB*DI*DS]; // pass1 final states [chunk][ch][16]
__device__ float g_sdt [(size_t)3*BB*DI];    // pass1 per-chunk sum(dt) [chunk][ch]

// bf16 split buffers for tensor-core GEMMs
__device__ __nv_bfloat16 g_xhi [(size_t)NR*DM];
__device__ __nv_bfloat16 g_xlo [(size_t)NR*DM];
__device__ __nv_bfloat16 g_w1hi[(size_t)XZW*DM];
__device__ __nv_bfloat16 g_w1lo[(size_t)XZW*DM];
__device__ __nv_bfloat16 g_xphi[(size_t)NR*DI];   // conv+silu output hi
__device__ __nv_bfloat16 g_xplo[(size_t)NR*DI];   // conv+silu output lo
__device__ __nv_bfloat16 g_w3hi[(size_t)128*DI];  // x_proj_w padded to 128 rows
__device__ __nv_bfloat16 g_w3lo[(size_t)128*DI];
__device__ __nv_bfloat16 g_dthi[(size_t)NR*DR];   // x_dbl[:, :64] hi (delta A)
__device__ __nv_bfloat16 g_dtlo[(size_t)NR*DR];
__device__ __nv_bfloat16 g_wdhi[(size_t)DI*DR];   // dt_proj_w hi/lo
__device__ __nv_bfloat16 g_wdlo[(size_t)DI*DR];
__device__ __nv_bfloat16 g_ghi [(size_t)NR*DI];
__device__ __nv_bfloat16 g_glo [(size_t)NR*DI];
__device__ __nv_bfloat16 g_w2hi[(size_t)DM*DI];
__device__ __nv_bfloat16 g_w2lo[(size_t)DM*DI];

__device__ __forceinline__ float siluf(float x) { return x / (1.0f + __expf(-x)); }
__device__ __forceinline__ float softplusf(float x) {
    return (x > 20.0f) ? x : log1pf(__expf(x));
}

// ===========================================================================
// Base-target (sm_103, no 'a') tensor path: ldmatrix + mma.sync + cp.async
// ===========================================================================
__device__ __forceinline__ uint32_t smem_u32(const void* p) {
    uint32_t a;
    asm("{ .reg .u64 t; cvta.to.shared.u64 t, %1; cvt.u32.u64 %0, t; }" : "=r"(a) : "l"(p));
    return a;
}
__device__ __forceinline__ void cpa16(uint32_t dst, const void* src) {
    asm volatile("cp.async.cg.shared.global [%0], [%1], 16;" :: "r"(dst), "l"(src));
}
__device__ __forceinline__ void ldsm4(uint32_t* r, uint32_t a) {
    asm volatile("ldmatrix.sync.aligned.m8n8.x4.shared.b16 {%0,%1,%2,%3}, [%4];"
                 : "=r"(r[0]), "=r"(r[1]), "=r"(r[2]), "=r"(r[3]) : "r"(a));
}
__device__ __forceinline__ void mma16816(float* c, const uint32_t* a, const uint32_t* b) {
    asm volatile("mma.sync.aligned.m16n8k16.row.col.f32.bf16.bf16.f32 "
                 "{%0,%1,%2,%3}, {%4,%5,%6,%7}, {%8,%9}, {%0,%1,%2,%3};"
                 : "+f"(c[0]), "+f"(c[1]), "+f"(c[2]), "+f"(c[3])
                 : "r"(a[0]), "r"(a[1]), "r"(a[2]), "r"(a[3]), "r"(b[0]), "r"(b[1]));
}

// ===========================================================================
// Split fp32 -> bf16 hi + bf16 lo (residual)
// ===========================================================================
__global__ void split_bf16(const float* __restrict__ in, __nv_bfloat16* __restrict__ hi,
                           __nv_bfloat16* __restrict__ lo, int n4)
{
    int i = blockIdx.x * blockDim.x + threadIdx.x;
    if (i >= n4) return;
    float4 v = *(const float4*)(in + (size_t)i * 4);
    __nv_bfloat16 h0 = __float2bfloat16(v.x), h1 = __float2bfloat16(v.y);
    __nv_bfloat16 h2 = __float2bfloat16(v.z), h3 = __float2bfloat16(v.w);
    __nv_bfloat16 l0 = __float2bfloat16(v.x - __bfloat162float(h0));
    __nv_bfloat16 l1 = __float2bfloat16(v.y - __bfloat162float(h1));
    __nv_bfloat16 l2 = __float2bfloat16(v.z - __bfloat162float(h2));
    __nv_bfloat16 l3 = __float2bfloat16(v.w - __bfloat162float(h3));
    __nv_bfloat162* hp = (__nv_bfloat162*)(hi + (size_t)i * 4);
    __nv_bfloat162* lp = (__nv_bfloat162*)(lo + (size_t)i * 4);
    hp[0] = __nv_bfloat162(h0, h1); hp[1] = __nv_bfloat162(h2, h3);
    lp[0] = __nv_bfloat162(l0, l1); lp[1] = __nv_bfloat162(l2, l3);
}

// Split + zero-pad x_proj_w [96,2048] -> [128,2048] bf16 hi/lo
__global__ void split_pad_xw(const float* __restrict__ xw)
{
    int i = blockIdx.x * blockDim.x + threadIdx.x;   // float4 index over [128][2048]
    if (i >= 128 * DI / 4) return;
    int row = i >> 9;                                // 512 float4 per row
    float4 v = make_float4(0.f, 0.f, 0.f, 0.f);
    if (row < 96) v = *(const float4*)(xw + (size_t)i * 4);
    __nv_bfloat16 h0 = __float2bfloat16(v.x), h1 = __float2bfloat16(v.y);
    __nv_bfloat16 h2 = __float2bfloat16(v.z), h3 = __float2bfloat16(v.w);
    __nv_bfloat162* hp = (__nv_bfloat162*)(g_w3hi + (size_t)i * 4);
    __nv_bfloat162* lp = (__nv_bfloat162*)(g_w3lo + (size_t)i * 4);
    hp[0] = __nv_bfloat162(h0, h1); hp[1] = __nv_bfloat162(h2, h3);
    lp[0] = __nv_bfloat162(__float2bfloat16(v.x - __bfloat162float(h0)),
                           __float2bfloat16(v.y - __bfloat162float(h1)));
    lp[1] = __nv_bfloat162(__float2bfloat16(v.z - __bfloat162float(h2)),
                           __float2bfloat16(v.w - __bfloat162float(h3)));
}

// ===========================================================================
// Split-bf16 HMMA GEMM v5: C[M,N] = A[M,K] @ B[N,K]^T, fp32 accumulate.
// CTA tile 128x128, warp tile 64x32 (8 warps, 2x4), stage K=16.
// v5: packed-32B rows + XOR swizzle (chunk ^= (row>>2)&1), 6-stage cp.async
// ring, ONE barrier per TWO K-stages (warps drift -> ldsm/MMA overlap),
// all 12 ldsm issued before the 48 MMAs of a stage. 2 CTAs/SM.
// Split-K via blockIdx.z (kChunk columns each, partial written at z*cStride).
// ===========================================================================
#define OA_LO 4096         // +128*32
#define OB_HI 8192
#define OB_LO 12288
#define STG   16384
#define NSTG  6
#define HM_SMEM (NSTG*STG) // 98304 per CTA -> 2 CTAs/SM

__global__ void __launch_bounds__(256, 2)
hmma_gemm(const __nv_bfloat16* __restrict__ Ahi, const __nv_bfloat16* __restrict__ Alo,
          const __nv_bfloat16* __restrict__ Bhi, const __nv_bfloat16* __restrict__ Blo,
          float* __restrict__ C, int N, int K, int kChunk, size_t cStride)
{
    extern __shared__ char sm_[];
    const uint32_t sb = smem_u32(sm_);
    const int tid = threadIdx.x, lane = tid & 31, wid = tid >> 5;
    const int wm = wid >> 2, wn = wid & 3;
    const int m0 = blockIdx.y * 128, n0 = blockIdx.x * 128;
    const int kOffB = blockIdx.z * kChunk * 2;      // byte offset along K
    C += (size_t)blockIdx.z * cStride;
    const int nst = kChunk >> 4;

    float acc[4][4][4];
    #pragma unroll
    for (int i = 0; i < 4; ++i)
        #pragma unroll
        for (int j = 0; j < 4; ++j)
            #pragma unroll
            for (int q = 0; q < 4; ++q) acc[i][j][q] = 0.0f;

    // cp.async write mapping: row lr, chunk ch; swizzled offset
    const int lr = wid * 16 + (lane & 7) + ((lane >> 4) << 3);
    const int ch = (lane >> 3) & 1;
    const uint32_t wo = (uint32_t)(lr * 32 + ((ch ^ ((lr >> 2) & 1)) << 4));
    const int gh = ch * 16;                          // byte offset in 32B k-slab
    const char* pAh = (const char*)(Ahi + (size_t)(m0 + lr) * K) + kOffB + gh;
    const char* pAl = (const char*)(Alo + (size_t)(m0 + lr) * K) + kOffB + gh;
    const char* pBh = (const char*)(Bhi + (size_t)(n0 + lr) * K) + kOffB + gh;
    const char* pBl = (const char*)(Blo + (size_t)(n0 + lr) * K) + kOffB + gh;

    auto load_stage = [&](int s) {
        if (s < nst) {
            const uint32_t st = sb + (uint32_t)(s % NSTG) * STG;
            const int kb = s * 32;
            cpa16(st + wo, pAh + kb);
            cpa16(st + OA_LO + wo, pAl + kb);
            cpa16(st + OB_HI + wo, pBh + kb);
            cpa16(st + OB_LO + wo, pBl + kb);
        }
        asm volatile("cp.async.commit_group;");
    };

    // prologue: 4 stages in flight
    load_stage(0);
    load_stage(1);
    load_stage(2);
    load_stage(3);

    // ldsm read offsets (swizzle preserved under +16-row steps)
    const int rowA = wm * 64 + (lane & 15);
    const int cA = lane >> 4;
    const uint32_t aOff = (uint32_t)(rowA * 32 + ((cA ^ ((rowA >> 2) & 1)) << 4));
    const int rowB = wn * 32 + (lane & 7) + ((lane >> 4) << 3);
    const int cB = (lane >> 3) & 1;
    const uint32_t bOff = (uint32_t)(rowB * 32 + ((cB ^ ((rowB >> 2) & 1)) << 4));

    auto process_stage = [&](int s) {
        const uint32_t st = sb + (uint32_t)(s % NSTG) * STG;
        const uint32_t aB = st + aOff;
        const uint32_t bB = st + OB_HI + bOff;

        uint32_t ah[4][4], al[4][4], bh[2][4], bl[2][4];
        ldsm4(bh[0], bB);
        ldsm4(bh[1], bB + 512);
        #pragma unroll
        for (int i = 0; i < 4; ++i) ldsm4(ah[i], aB + i * 512);
        #pragma unroll
        for (int i = 0; i < 4; ++i) ldsm4(al[i], aB + OA_LO + i * 512);
        ldsm4(bl[0], bB + (OB_LO - OB_HI));
        ldsm4(bl[1], bB + (OB_LO - OB_HI) + 512);

        #pragma unroll
        for (int i = 0; i < 4; ++i)
            #pragma unroll
            for (int j = 0; j < 4; ++j)
                mma16816(acc[i][j], ah[i], &bh[j >> 1][(j & 1) * 2]);
        #pragma unroll
        for (int i = 0; i < 4; ++i)
            #pragma unroll
            for (int j = 0; j < 4; ++j)
                mma16816(acc[i][j], al[i], &bh[j >> 1][(j & 1) * 2]);
        #pragma unroll
        for (int i = 0; i < 4; ++i)
            #pragma unroll
            for (int j = 0; j < 4; ++j)
                mma16816(acc[i][j], ah[i], &bl[j >> 1][(j & 1) * 2]);
    };

    for (int p = 0; p < (nst >> 1); ++p) {
        asm volatile("cp.async.wait_group 2;");
        __syncthreads();
        load_stage(2*p + 4);
        load_stage(2*p + 5);
        process_stage(2*p);
        process_stage(2*p + 1);
    }

    // epilogue: fp32 direct to global
    #pragma unroll
    for (int i = 0; i < 4; ++i)
        #pragma unroll
        for (int j = 0; j < 4; ++j) {
            int row = m0 + wm*64 + i*16 + (lane >> 2);
            int col = n0 + wn*32 + j*8 + (lane & 3)*2;
            *(float2*)(C + (size_t)row * N + col) =
                make_float2(acc[i][j][0], acc[i][j][1]);
            *(float2*)(C + (size_t)(row + 8) * N + col) =
                make_float2(acc[i][j][2], acc[i][j][3]);
        }
}

// Reduce xproj split-K partials: g_xdbl[m][c] = sum_z g_xpart[z][m][c], c<96.
// Also emits bf16 hi/lo of cols 0..63 (delta GEMM A operand).
__global__ void reduce_xdbl()
{
    int idx = blockIdx.x * blockDim.x + threadIdx.x;   // 0 .. 4096*24-1
    if (idx >= NR * 24) return;
    int m = idx / 24, c = (idx % 24) * 4;
    const float* p = g_xpart + (size_t)m * 128 + c;
    float4 s = make_float4(0.f, 0.f, 0.f, 0.f);
    #pragma unroll
    for (int z = 0; z < 8; ++z) {
        float4 v = *(const float4*)(p + (size_t)z * NR * 128);
        s.x += v.x; s.y += v.y; s.z += v.z; s.w += v.w;
    }
    *(float4*)(g_xdbl + (size_t)m * XD + c) = s;
    if (c < DR) {
        __nv_bfloat16 h0 = __float2bfloat16(s.x), h1 = __float2bfloat16(s.y);
        __nv_bfloat16 h2 = __float2bfloat16(s.z), h3 = __float2bfloat16(s.w);
        __nv_bfloat162* hp = (__nv_bfloat162*)(g_dthi + (size_t)m * DR + c);
        __nv_bfloat162* lp = (__nv_bfloat162*)(g_dtlo + (size_t)m * DR + c);
        hp[0] = __nv_bfloat162(h0, h1); hp[1] = __nv_bfloat162(h2, h3);
        lp[0] = __nv_bfloat162(__float2bfloat16(s.x - __bfloat162float(h0)),
                               __float2bfloat16(s.y - __bfloat162float(h1)));
        lp[1] = __nv_bfloat162(__float2bfloat16(s.z - __bfloat162float(h2)),
                               __float2bfloat16(s.w - __bfloat162float(h3)));
    }
}

// ---------------------------------------------------------------------------
// Causal depthwise conv (width 4) + bias + silu over xz[:, :, 0:DI].
// Writes bf16 hi/lo [B,L,DI] (for xproj HMMA) and fp32 transposed [B,DI,L].
// ---------------------------------------------------------------------------
__global__ void conv_silu_kernel(const float* __restrict__ conv_w,
                                 const float* __restrict__ conv_b)
{
    __shared__ float sIn[35][33];
    __shared__ float sOut[32][33];
    const int b = blockIdx.z, d0 = blockIdx.y * 32, l0 = blockIdx.x * 32;
    const int tid = threadIdx.x, tx = tid & 31, ty = tid >> 5;

    for (int r = ty; r < 35; r += 8) {
        int gl = l0 + r - 3;
        sIn[r][tx] = (gl >= 0) ? g_xz[(size_t)(b*LL + gl) * XZW + d0 + tx] : 0.0f;
    }
    __syncthreads();

    float4 w = *(const float4*)(conv_w + (d0 + tx) * 4);
    float cb = conv_b[d0 + tx];
    #pragma unroll
    for (int i = 0; i < 4; ++i) {
        int r = ty + i * 8;
        float v = sIn[r][tx]*w.x + sIn[r+1][tx]*w.y + sIn[r+2][tx]*w.z + sIn[r+3][tx]*w.w + cb;
        v = siluf(v);
        sOut[r][tx] = v;
        size_t idx = (size_t)(b*LL + l0 + r) * DI + d0 + tx;
        __nv_bfloat16 h = __float2bfloat16(v);
        g_xphi[idx] = h;
        g_xplo[idx] = __float2bfloat16(v - __bfloat162float(h));
    }
    __syncthreads();
    #pragma unroll
    for (int i = 0; i < 4; ++i) {
        int dd = ty + i * 8;
        g_xpt[(size_t)(b*DI + d0 + dd) * LL + l0 + tx] = sOut[tx][dd];
    }
}

// ---------------------------------------------------------------------------
// delta transpose + bias + softplus:
// g_dtt[(b*DI+n)*LL + l] = softplus(g_delta[(b*LL+l)*DI + n] + dtb[n])
// ---------------------------------------------------------------------------
__global__ void dtrans_kernel(const float* __restrict__ dtb)
{
    __shared__ float sD[32][33];
    const int b = blockIdx.z, n0 = blockIdx.y * 32, l0 = blockIdx.x * 32;
    const int tid = threadIdx.x, tx = tid & 31, ty = tid >> 5;

    #pragma unroll
    for (int i = 0; i < 4; ++i) {
        int r = ty + i * 8;   // local l
        sD[r][tx] = g_delta[(size_t)(b*LL + l0 + r) * DI + n0 + tx];
    }
    __syncthreads();
    #pragma unroll
    for (int i = 0; i < 4; ++i) {
        int ny = ty + i * 8;  // local n
        int n = n0 + ny;
        float v = softplusf(sD[tx][ny] + dtb[n]);
        g_dtt[(size_t)(b*DI + n) * LL + l0 + tx] = v;
    }
}

// ---------------------------------------------------------------------------
// Chunked selective scan, pass 1: per-chunk final state q_c and sum(dt).
// ---------------------------------------------------------------------------
__global__ __launch_bounds__(256)
void scan_pass1(const float* __restrict__ A_log)
{
    const int tid = threadIdx.x;
    const int ch = blockIdx.x * 32 + (tid >> 3);
    const int g  = tid & 7;
    const int c  = blockIdx.y;            // 0..2
    const int d  = ch & (DI - 1);
    const int b  = ch >> 11;
    const int n0 = g * 2;

    const float A0 = -__expf(A_log[d*DS + n0]);
    const float A1 = -__expf(A_log[d*DS + n0 + 1]);

    const float* __restrict__ dtp = g_dtt + (size_t)ch * LL + c * LC;
    const float* __restrict__ xpp = g_xpt + (size_t)ch * LL + c * LC;
    const float* __restrict__ rp  = g_xdbl + (size_t)(b*LL + c*LC) * XD + DR + n0;

    float h0 = 0.f, h1 = 0.f, sdt = 0.f;
    float dt[2][4], xv[2][4];
    float2 Bv[2][4];

    #pragma unroll
    for (int u = 0; u < 4; ++u) {
        dt[0][u] = __ldg(dtp + u);
        xv[0][u] = __ldg(xpp + u);
        Bv[0][u] = *(const float2*)(rp + (size_t)u * XD);
    }

    for (int l = 0; l < LC; l += 8) {
        #pragma unroll
        for (int u = 0; u < 4; ++u) {
            int ll = l + 4 + u;
            dt[1][u] = __ldg(dtp + ll);
            xv[1][u] = __ldg(xpp + ll);
            Bv[1][u] = *(const float2*)(rp + (size_t)ll * XD);
        }
        #pragma unroll
        for (int u = 0; u < 4; ++u) {
            float dtx = dt[0][u] * xv[0][u];
            h0 = fmaf(__expf(dt[0][u] * A0), h0, dtx * Bv[0][u].x);
            h1 = fmaf(__expf(dt[0][u] * A1), h1, dtx * Bv[0][u].y);
            sdt += dt[0][u];
        }
        int lp = (l + 8 < LC) ? l + 8 : 0;    // clamped prefetch (last unused)
        #pragma unroll
        for (int u = 0; u < 4; ++u) {
            int ll = lp + u;
            dt[0][u] = __ldg(dtp + ll);
            xv[0][u] = __ldg(xpp + ll);
            Bv[0][u] = *(const float2*)(rp + (size_t)ll * XD);
        }
        #pragma unroll
        for (int u = 0; u < 4; ++u) {
            float dtx = dt[1][u] * xv[1][u];
            h0 = fmaf(__expf(dt[1][u] * A0), h0, dtx * Bv[1][u].x);
            h1 = fmaf(__expf(dt[1][u] * A1), h1, dtx * Bv[1][u].y);
            sdt += dt[1][u];
        }
    }

    float* qp = g_q + ((size_t)c * (BB*DI) + ch) * DS + n0;
    qp[0] = h0; qp[1] = h1;
    if (g == 0) g_sdt[(size_t)c * (BB*DI) + ch] = sdt;
}

// ---------------------------------------------------------------------------
// Chunked selective scan, pass 2: carry-in from pass1, full y output.
// ---------------------------------------------------------------------------
__global__ __launch_bounds__(256)
void scan_pass2(const float* __restrict__ A_log, const float* __restrict__ Dv)
{
    const int tid = threadIdx.x;
    const int ch = blockIdx.x * 32 + (tid >> 3);
    const int g  = tid & 7;
    const int c  = blockIdx.y;            // 0..3
    const int d  = ch & (DI - 1);
    const int b  = ch >> 11;
    const int n0 = g * 2;

    const float A0 = -__expf(A_log[d*DS + n0]);
    const float A1 = -__expf(A_log[d*DS + n0 + 1]);
    const float Dd = Dv[d];

    float h0 = 0.f, h1 = 0.f;
    for (int j = 0; j < c; ++j) {
        float s = __ldg(g_sdt + (size_t)j * (BB*DI) + ch);
        const float* qp = g_q + ((size_t)j * (BB*DI) + ch) * DS + n0;
        h0 = fmaf(__expf(s * A0), h0, __ldg(qp));
        h1 = fmaf(__expf(s * A1), h1, __ldg(qp + 1));
    }

    const float* __restrict__ dtp = g_dtt + (size_t)ch * LL + c * LC;
    const float* __restrict__ xpp = g_xpt + (size_t)ch * LL + c * LC;
    const float* __restrict__ rp  = g_xdbl + (size_t)(b*LL + c*LC) * XD + DR + n0;
    float* __restrict__ yp = g_yt + (size_t)ch * LL + c * LC;

    float dt[2][4], xv[2][4];
    float2 Bv[2][4], Cv[2][4];

    #pragma unroll
    for (int u = 0; u < 4; ++u) {
        dt[0][u] = __ldg(dtp + u);
        xv[0][u] = __ldg(xpp + u);
        Bv[0][u] = *(const float2*)(rp + (size_t)u * XD);
        Cv[0][u] = *(const float2*)(rp + (size_t)u * XD + DS);
    }

    for (int l = 0; l < LC; l += 8) {
        #pragma unroll
        for (int u = 0; u < 4; ++u) {
            int ll = l + 4 + u;
            dt[1][u] = __ldg(dtp + ll);
            xv[1][u] = __ldg(xpp + ll);
            Bv[1][u] = *(const float2*)(rp + (size_t)ll * XD);
            Cv[1][u] = *(const float2*)(rp + (size_t)ll * XD + DS);
        }
        #pragma unroll
        for (int u = 0; u < 4; ++u) {
            float dtx = dt[0][u] * xv[0][u];
            h0 = fmaf(__expf(dt[0][u] * A0), h0, dtx * Bv[0][u].x);
            h1 = fmaf(__expf(dt[0][u] * A1), h1, dtx * Bv[0][u].y);
            float y = fmaf(h0, Cv[0][u].x, h1 * Cv[0][u].y);
            y += __shfl_down_sync(0xffffffffu, y, 4, 8);
            y += __shfl_down_sync(0xffffffffu, y, 2, 8);
            y += __shfl_down_sync(0xffffffffu, y, 1, 8);
            if (g == 0) yp[l + u] = fmaf(Dd, xv[0][u], y);
        }
        int lp = (l + 8 < LC) ? l + 8 : 0;
        #pragma unroll
        for (int u = 0; u < 4; ++u) {
            int ll = lp + u;
            dt[0][u] = __ldg(dtp + ll);
            xv[0][u] = __ldg(xpp + ll);
            Bv[0][u] = *(const float2*)(rp + (size_t)ll * XD);
            Cv[0][u] = *(const float2*)(rp + (size_t)ll * XD + DS);
        }
        #pragma unroll
        for (int u = 0; u < 4; ++u) {
            float dtx = dt[1][u] * xv[1][u];
            h0 = fmaf(__expf(dt[1][u] * A0), h0, dtx * Bv[1][u].x);
            h1 = fmaf(__expf(dt[1][u] * A1), h1, dtx * Bv[1][u].y);
            float y = fmaf(h0, Cv[1][u].x, h1 * Cv[1][u].y);
            y += __shfl_down_sync(0xffffffffu, y, 4, 8);
            y += __shfl_down_sync(0xffffffffu, y, 2, 8);
            y += __shfl_down_sync(0xffffffffu, y, 1, 8);
            if (g == 0) yp[l + 4 + u] = fmaf(Dd, xv[1][u], y);
        }
    }
}

// ---------------------------------------------------------------------------
// g = y_t * silu(z), fused with bf16 hi/lo split (feeds out_proj HMMA)
// ---------------------------------------------------------------------------
__global__ void gmul_split_kernel()
{
    __shared__ float sY[32][33];
    const int b = blockIdx.z, d0 = blockIdx.y * 32, l0 = blockIdx.x * 32;
    const int tid = threadIdx.x, tx = tid & 31, ty = tid >> 5;

    #pragma unroll
    for (int i = 0; i < 4; ++i) {
        int dd = ty + i * 8;
        sY[dd][tx] = g_yt[(size_t)(b*DI + d0 + dd) * LL + l0 + tx];
    }
    __syncthreads();
    #pragma unroll
    for (int i = 0; i < 4; ++i) {
        int r = ty + i * 8;
        size_t idx = (size_t)(b*LL + l0 + r) * DI + d0 + tx;
        float z = g_xz[(size_t)(b*LL + l0 + r) * XZW + DI + d0 + tx];
        float v = sY[tx][r] * siluf(z);
        __nv_bfloat16 h = __float2bfloat16(v);
        g_ghi[idx] = h;
        g_glo[idx] = __float2bfloat16(v - __bfloat162float(h));
    }
}

// ---------------------------------------------------------------------------
extern "C" void kernel_launch(void* const* d_in, const int* in_sizes, int n_in,
                              void* d_out, int out_size)
{
    const float* x       = (const float*)d_in[0];
    const float* in_proj = (const float*)d_in[1];
    const float* conv_w  = (const float*)d_in[2];
    const float* conv_b  = (const float*)d_in[3];
    const float* x_proj  = (const float*)d_in[4];
    const float* dt_w    = (const float*)d_in[5];
    const float* dt_b    = (const float*)d_in[6];
    const float* A_log   = (const float*)d_in[7];
    const float* Dv      = (const float*)d_in[8];
    const float* out_w   = (const float*)d_in[9];
    float* out = (float*)d_out;

    float *xz, *xpart, *delta;
    __nv_bfloat16 *xhi, *xlo, *w1hi, *w1lo, *xphi, *xplo, *w3hi, *w3lo;
    __nv_bfloat16 *dthi, *dtlo, *wdhi, *wdlo, *ghi, *glo, *w2hi, *w2lo;
    cudaGetSymbolAddress((void**)&xz,    g_xz);
    cudaGetSymbolAddress((void**)&xpart, g_xpart);
    cudaGetSymbolAddress((void**)&delta, g_delta);
    cudaGetSymbolAddress((void**)&xhi,   g_xhi);
    cudaGetSymbolAddress((void**)&xlo,   g_xlo);
    cudaGetSymbolAddress((void**)&w1hi,  g_w1hi);
    cudaGetSymbolAddress((void**)&w1lo,  g_w1lo);
    cudaGetSymbolAddress((void**)&xphi,  g_xphi);
    cudaGetSymbolAddress((void**)&xplo,  g_xplo);
    cudaGetSymbolAddress((void**)&w3hi,  g_w3hi);
    cudaGetSymbolAddress((void**)&w3lo,  g_w3lo);
    cudaGetSymbolAddress((void**)&dthi,  g_dthi);
    cudaGetSymbolAddress((void**)&dtlo,  g_dtlo);
    cudaGetSymbolAddress((void**)&wdhi,  g_wdhi);
    cudaGetSymbolAddress((void**)&wdlo,  g_wdlo);
    cudaGetSymbolAddress((void**)&ghi,   g_ghi);
    cudaGetSymbolAddress((void**)&glo,   g_glo);
    cudaGetSymbolAddress((void**)&w2hi,  g_w2hi);
    cudaGetSymbolAddress((void**)&w2lo,  g_w2lo);

    cudaFuncSetAttribute(hmma_gemm, cudaFuncAttributeMaxDynamicSharedMemorySize, HM_SMEM);

    // 0-2) splits (so in_proj hmma sits at launch index 3 for ncu)
    split_bf16<<<(NR*DM/4 + 255)/256, 256>>>(x, xhi, xlo, NR*DM/4);
    split_bf16<<<(XZW*DM/4 + 255)/256, 256>>>(in_proj, w1hi, w1lo, XZW*DM/4);
    split_bf16<<<(DM*DI/4 + 255)/256, 256>>>(out_w, w2hi, w2lo, DM*DI/4);
    // 3) xz = x @ in_proj_w^T  -> [4096, 4096]
    hmma_gemm<<<dim3(XZW/128, NR/128, 1), 256, HM_SMEM>>>(
        xhi, xlo, w1hi, w1lo, xz, XZW, DM, DM, 0);
    // 4) conv + silu (writes bf16 hi/lo + fp32 transposed)
    conv_silu_kernel<<<dim3(LL/32, DI/32, BB), 256>>>(conv_w, conv_b);
    // 5) pad+split x_proj_w; split dt_proj_w
    split_pad_xw<<<(128*DI/4 + 255)/256, 256>>>(x_proj);
    split_bf16<<<(DI*DR/4 + 255)/256, 256>>>(dt_w, wdhi, wdlo, DI*DR/4);
    // 6) x_dbl partials = x_p @ x_proj_w^T (split-K over 8 chunks of 256)
    hmma_gemm<<<dim3(1, NR/128, 8), 256, HM_SMEM>>>(
        xphi, xplo, w3hi, w3lo, xpart, 128, DI, DI/8, (size_t)NR*128);
    // 7) reduce partials -> g_xdbl; also bf16-split delta cols
    reduce_xdbl<<<(NR*24 + 255)/256, 256>>>();
    // 8) delta raw = x_dbl[:, :64] @ dt_proj_w^T (HMMA) -> [4096, 2048]
    hmma_gemm<<<dim3(DI/128, NR/128, 1), 256, HM_SMEM>>>(
        dthi, dtlo, wdhi, wdlo, delta, DI, DR, DR, 0);
    // 9) softplus(delta + bias), transposed to [B,DI,L]
    dtrans_kernel<<<dim3(LL/32, DI/32, BB), 256>>>(dt_b);
    // 10) chunked selective scan (2 passes)
    scan_pass1<<<dim3((BB*DI)/32, NCH-1), 256>>>(A_log);
    scan_pass2<<<dim3((BB*DI)/32, NCH), 256>>>(A_log, Dv);
    // 11) g = y * silu(z) fused with bf16 split
    gmul_split_kernel<<<dim3(LL/32, DI/32, BB), 256>>>();
    // 12) out = g @ out_proj_w^T
    hmma_gemm<<<dim3(DM/128, NR/128, 1), 256, HM_SMEM>>>(
        ghi, glo, w2hi, w2lo, out, DM, DI, DI, 0);
}

// round 12
// speedup vs baseline: 1.1291x; 1.0818x over previous
#include <cuda_runtime.h>
#include <cuda_bf16.h>
#include <cstdint>
#include <math.h>

// Problem constants (fixed by reference)
#define BB 2
#define LL 2048
#define DM 1024
#define DI 2048
#define DS 16
#define DR 64
#define NR (BB*LL)     // 4096 rows (b,l)
#define XZW (2*DI)     // 4096
#define XD  96         // dt_rank + 2*d_state
#define NCH 8
#define LC (LL/NCH)    // 256

// Scratch (device globals; no allocation allowed)
__device__ float g_xz  [(size_t)NR*XZW];   // in_proj output [B,L,2*DI]
__device__ float g_xpt [(size_t)BB*DI*LL]; // conv+silu output transposed [B,DI,L]
__device__ float g_xdbl[(size_t)NR*XD];    // x_proj output [B,L,96]
__device__ float g_dtt [(size_t)BB*DI*LL]; // softplus(delta) transposed [B,DI,L]
__device__ float g_yt  [(size_t)BB*DI*LL]; // scan output (+D*x) [B,DI,L]
__device__ float g_xpart[(size_t)8*NR*128];// xproj split-K partials [8][4096][128]
__device__ float g_delta[(size_t)NR*DI];   // raw delta GEMM output [B,L,DI]
__device__ float g_q   [(size_t)(NCH-1)*BB*DI*DS]; // pass1 final states [chunk][ch][16]
__device__ float g_sdt [(size_t)(NCH-1)*BB*DI];    // pass1 per-chunk sum(dt) [chunk][ch]

// bf16 split buffers for tensor-core GEMMs
__device__ __nv_bfloat16 g_xhi [(size_t)NR*DM];
__device__ __nv_bfloat16 g_xlo [(size_t)NR*DM];
__device__ __nv_bfloat16 g_w1hi[(size_t)XZW*DM];
__device__ __nv_bfloat16 g_w1lo[(size_t)XZW*DM];
__device__ __nv_bfloat16 g_xphi[(size_t)NR*DI];   // conv+silu output hi
__device__ __nv_bfloat16 g_xplo[(size_t)NR*DI];   // conv+silu output lo
__device__ __nv_bfloat16 g_w3hi[(size_t)128*DI];  // x_proj_w padded to 128 rows
__device__ __nv_bfloat16 g_w3lo[(size_t)128*DI];
__device__ __nv_bfloat16 g_dthi[(size_t)NR*DR];   // x_dbl[:, :64] hi (delta A)
__device__ __nv_bfloat16 g_dtlo[(size_t)NR*DR];
__device__ __nv_bfloat16 g_wdhi[(size_t)DI*DR];   // dt_proj_w hi/lo
__device__ __nv_bfloat16 g_wdlo[(size_t)DI*DR];
__device__ __nv_bfloat16 g_ghi [(size_t)NR*DI];
__device__ __nv_bfloat16 g_glo [(size_t)NR*DI];
__device__ __nv_bfloat16 g_w2hi[(size_t)DM*DI];
__device__ __nv_bfloat16 g_w2lo[(size_t)DM*DI];

__device__ __forceinline__ float siluf(float x) { return x / (1.0f + __expf(-x)); }
__device__ __forceinline__ float softplusf(float x) {
    return (x > 20.0f) ? x : log1pf(__expf(x));
}

// ===========================================================================
// Base-target (sm_103, no 'a') tensor path: ldmatrix + mma.sync + cp.async
// ===========================================================================
__device__ __forceinline__ uint32_t smem_u32(const void* p) {
    uint32_t a;
    asm("{ .reg .u64 t; cvta.to.shared.u64 t, %1; cvt.u32.u64 %0, t; }" : "=r"(a) : "l"(p));
    return a;
}
__device__ __forceinline__ void cpa16(uint32_t dst, const void* src) {
    asm volatile("cp.async.cg.shared.global [%0], [%1], 16;" :: "r"(dst), "l"(src));
}
__device__ __forceinline__ void ldsm4(uint32_t* r, uint32_t a) {
    asm volatile("ldmatrix.sync.aligned.m8n8.x4.shared.b16 {%0,%1,%2,%3}, [%4];"
                 : "=r"(r[0]), "=r"(r[1]), "=r"(r[2]), "=r"(r[3]) : "r"(a));
}
__device__ __forceinline__ void mma16816(float* c, const uint32_t* a, const uint32_t* b) {
    asm volatile("mma.sync.aligned.m16n8k16.row.col.f32.bf16.bf16.f32 "
                 "{%0,%1,%2,%3}, {%4,%5,%6,%7}, {%8,%9}, {%0,%1,%2,%3};"
                 : "+f"(c[0]), "+f"(c[1]), "+f"(c[2]), "+f"(c[3])
                 : "r"(a[0]), "r"(a[1]), "r"(a[2]), "r"(a[3]), "r"(b[0]), "r"(b[1]));
}

// ===========================================================================
// Split fp32 -> bf16 hi + bf16 lo (residual)
// ===========================================================================
__global__ void split_bf16(const float* __restrict__ in, __nv_bfloat16* __restrict__ hi,
                           __nv_bfloat16* __restrict__ lo, int n4)
{
    int i = blockIdx.x * blockDim.x + threadIdx.x;
    if (i >= n4) return;
    float4 v = *(const float4*)(in + (size_t)i * 4);
    __nv_bfloat16 h0 = __float2bfloat16(v.x), h1 = __float2bfloat16(v.y);
    __nv_bfloat16 h2 = __float2bfloat16(v.z), h3 = __float2bfloat16(v.w);
    __nv_bfloat16 l0 = __float2bfloat16(v.x - __bfloat162float(h0));
    __nv_bfloat16 l1 = __float2bfloat16(v.y - __bfloat162float(h1));
    __nv_bfloat16 l2 = __float2bfloat16(v.z - __bfloat162float(h2));
    __nv_bfloat16 l3 = __float2bfloat16(v.w - __bfloat162float(h3));
    __nv_bfloat162* hp = (__nv_bfloat162*)(hi + (size_t)i * 4);
    __nv_bfloat162* lp = (__nv_bfloat162*)(lo + (size_t)i * 4);
    hp[0] = __nv_bfloat162(h0, h1); hp[1] = __nv_bfloat162(h2, h3);
    lp[0] = __nv_bfloat162(l0, l1); lp[1] = __nv_bfloat162(l2, l3);
}

// Split + zero-pad x_proj_w [96,2048] -> [128,2048] bf16 hi/lo
__global__ void split_pad_xw(const float* __restrict__ xw)
{
    int i = blockIdx.x * blockDim.x + threadIdx.x;   // float4 index over [128][2048]
    if (i >= 128 * DI / 4) return;
    int row = i >> 9;                                // 512 float4 per row
    float4 v = make_float4(0.f, 0.f, 0.f, 0.f);
    if (row < 96) v = *(const float4*)(xw + (size_t)i * 4);
    __nv_bfloat16 h0 = __float2bfloat16(v.x), h1 = __float2bfloat16(v.y);
    __nv_bfloat16 h2 = __float2bfloat16(v.z), h3 = __float2bfloat16(v.w);
    __nv_bfloat162* hp = (__nv_bfloat162*)(g_w3hi + (size_t)i * 4);
    __nv_bfloat162* lp = (__nv_bfloat162*)(g_w3lo + (size_t)i * 4);
    hp[0] = __nv_bfloat162(h0, h1); hp[1] = __nv_bfloat162(h2, h3);
    lp[0] = __nv_bfloat162(__float2bfloat16(v.x - __bfloat162float(h0)),
                           __float2bfloat16(v.y - __bfloat162float(h1)));
    lp[1] = __nv_bfloat162(__float2bfloat16(v.z - __bfloat162float(h2)),
                           __float2bfloat16(v.w - __bfloat162float(h3)));
}

// ===========================================================================
// Split-bf16 HMMA GEMM v5: C[M,N] = A[M,K] @ B[N,K]^T, fp32 accumulate.
// CTA tile 128x128, warp tile 64x32 (8 warps, 2x4), stage K=16.
// v5: packed-32B rows + XOR swizzle (chunk ^= (row>>2)&1), 6-stage cp.async
// ring, ONE barrier per TWO K-stages (warps drift -> ldsm/MMA overlap),
// all 12 ldsm issued before the 48 MMAs of a stage. 2 CTAs/SM.
// Split-K via blockIdx.z (kChunk columns each, partial written at z*cStride).
// ===========================================================================
#define OA_LO 4096         // +128*32
#define OB_HI 8192
#define OB_LO 12288
#define STG   16384
#define NSTG  6
#define HM_SMEM (NSTG*STG) // 98304 per CTA -> 2 CTAs/SM

__global__ void __launch_bounds__(256, 2)
hmma_gemm(const __nv_bfloat16* __restrict__ Ahi, const __nv_bfloat16* __restrict__ Alo,
          const __nv_bfloat16* __restrict__ Bhi, const __nv_bfloat16* __restrict__ Blo,
          float* __restrict__ C, int N, int K, int kChunk, size_t cStride)
{
    extern __shared__ char sm_[];
    const uint32_t sb = smem_u32(sm_);
    const int tid = threadIdx.x, lane = tid & 31, wid = tid >> 5;
    const int wm = wid >> 2, wn = wid & 3;
    const int m0 = blockIdx.y * 128, n0 = blockIdx.x * 128;
    const int kOffB = blockIdx.z * kChunk * 2;      // byte offset along K
    C += (size_t)blockIdx.z * cStride;
    const int nst = kChunk >> 4;

    float acc[4][4][4];
    #pragma unroll
    for (int i = 0; i < 4; ++i)
        #pragma unroll
        for (int j = 0; j < 4; ++j)
            #pragma unroll
            for (int q = 0; q < 4; ++q) acc[i][j][q] = 0.0f;

    // cp.async write mapping: row lr, chunk ch; swizzled offset
    const int lr = wid * 16 + (lane & 7) + ((lane >> 4) << 3);
    const int ch = (lane >> 3) & 1;
    const uint32_t wo = (uint32_t)(lr * 32 + ((ch ^ ((lr >> 2) & 1)) << 4));
    const int gh = ch * 16;                          // byte offset in 32B k-slab
    const char* pAh = (const char*)(Ahi + (size_t)(m0 + lr) * K) + kOffB + gh;
    const char* pAl = (const char*)(Alo + (size_t)(m0 + lr) * K) + kOffB + gh;
    const char* pBh = (const char*)(Bhi + (size_t)(n0 + lr) * K) + kOffB + gh;
    const char* pBl = (const char*)(Blo + (size_t)(n0 + lr) * K) + kOffB + gh;

    auto load_stage = [&](int s) {
        if (s < nst) {
            const uint32_t st = sb + (uint32_t)(s % NSTG) * STG;
            const int kb = s * 32;
            cpa16(st + wo, pAh + kb);
            cpa16(st + OA_LO + wo, pAl + kb);
            cpa16(st + OB_HI + wo, pBh + kb);
            cpa16(st + OB_LO + wo, pBl + kb);
        }
        asm volatile("cp.async.commit_group;");
    };

    // prologue: 4 stages in flight
    load_stage(0);
    load_stage(1);
    load_stage(2);
    load_stage(3);

    // ldsm read offsets (swizzle preserved under +16-row steps)
    const int rowA = wm * 64 + (lane & 15);
    const int cA = lane >> 4;
    const uint32_t aOff = (uint32_t)(rowA * 32 + ((cA ^ ((rowA >> 2) & 1)) << 4));
    const int rowB = wn * 32 + (lane & 7) + ((lane >> 4) << 3);
    const int cB = (lane >> 3) & 1;
    const uint32_t bOff = (uint32_t)(rowB * 32 + ((cB ^ ((rowB >> 2) & 1)) << 4));

    auto process_stage = [&](int s) {
        const uint32_t st = sb + (uint32_t)(s % NSTG) * STG;
        const uint32_t aB = st + aOff;
        const uint32_t bB = st + OB_HI + bOff;

        uint32_t ah[4][4], al[4][4], bh[2][4], bl[2][4];
        ldsm4(bh[0], bB);
        ldsm4(bh[1], bB + 512);
        #pragma unroll
        for (int i = 0; i < 4; ++i) ldsm4(ah[i], aB + i * 512);
        #pragma unroll
        for (int i = 0; i < 4; ++i) ldsm4(al[i], aB + OA_LO + i * 512);
        ldsm4(bl[0], bB + (OB_LO - OB_HI));
        ldsm4(bl[1], bB + (OB_LO - OB_HI) + 512);

        #pragma unroll
        for (int i = 0; i < 4; ++i)
            #pragma unroll
            for (int j = 0; j < 4; ++j)
                mma16816(acc[i][j], ah[i], &bh[j >> 1][(j & 1) * 2]);
        #pragma unroll
        for (int i = 0; i < 4; ++i)
            #pragma unroll
            for (int j = 0; j < 4; ++j)
                mma16816(acc[i][j], al[i], &bh[j >> 1][(j & 1) * 2]);
        #pragma unroll
        for (int i = 0; i < 4; ++i)
            #pragma unroll
            for (int j = 0; j < 4; ++j)
                mma16816(acc[i][j], ah[i], &bl[j >> 1][(j & 1) * 2]);
    };

    for (int p = 0; p < (nst >> 1); ++p) {
        asm volatile("cp.async.wait_group 2;");
        __syncthreads();
        load_stage(2*p + 4);
        load_stage(2*p + 5);
        process_stage(2*p);
        process_stage(2*p + 1);
    }

    // epilogue: fp32 direct to global
    #pragma unroll
    for (int i = 0; i < 4; ++i)
        #pragma unroll
        for (int j = 0; j < 4; ++j) {
            int row = m0 + wm*64 + i*16 + (lane >> 2);
            int col = n0 + wn*32 + j*8 + (lane & 3)*2;
            *(float2*)(C + (size_t)row * N + col) =
                make_float2(acc[i][j][0], acc[i][j][1]);
            *(float2*)(C + (size_t)(row + 8) * N + col) =
                make_float2(acc[i][j][2], acc[i][j][3]);
        }
}

// Reduce xproj split-K partials: g_xdbl[m][c] = sum_z g_xpart[z][m][c], c<96.
// Also emits bf16 hi/lo of cols 0..63 (delta GEMM A operand).
__global__ void reduce_xdbl()
{
    int idx = blockIdx.x * blockDim.x + threadIdx.x;   // 0 .. 4096*24-1
    if (idx >= NR * 24) return;
    int m = idx / 24, c = (idx % 24) * 4;
    const float* p = g_xpart + (size_t)m * 128 + c;
    float4 s = make_float4(0.f, 0.f, 0.f, 0.f);
    #pragma unroll
    for (int z = 0; z < 8; ++z) {
        float4 v = *(const float4*)(p + (size_t)z * NR * 128);
        s.x += v.x; s.y += v.y; s.z += v.z; s.w += v.w;
    }
    *(float4*)(g_xdbl + (size_t)m * XD + c) = s;
    if (c < DR) {
        __nv_bfloat16 h0 = __float2bfloat16(s.x), h1 = __float2bfloat16(s.y);
        __nv_bfloat16 h2 = __float2bfloat16(s.z), h3 = __float2bfloat16(s.w);
        __nv_bfloat162* hp = (__nv_bfloat162*)(g_dthi + (size_t)m * DR + c);
        __nv_bfloat162* lp = (__nv_bfloat162*)(g_dtlo + (size_t)m * DR + c);
        hp[0] = __nv_bfloat162(h0, h1); hp[1] = __nv_bfloat162(h2, h3);
        lp[0] = __nv_bfloat162(__float2bfloat16(s.x - __bfloat162float(h0)),
                               __float2bfloat16(s.y - __bfloat162float(h1)));
        lp[1] = __nv_bfloat162(__float2bfloat16(s.z - __bfloat162float(h2)),
                               __float2bfloat16(s.w - __bfloat162float(h3)));
    }
}

// ---------------------------------------------------------------------------
// Causal depthwise conv (width 4) + bias + silu over xz[:, :, 0:DI].
// Writes bf16 hi/lo [B,L,DI] (for xproj HMMA) and fp32 transposed [B,DI,L].
// ---------------------------------------------------------------------------
__global__ void conv_silu_kernel(const float* __restrict__ conv_w,
                                 const float* __restrict__ conv_b)
{
    __shared__ float sIn[35][33];
    __shared__ float sOut[32][33];
    const int b = blockIdx.z, d0 = blockIdx.y * 32, l0 = blockIdx.x * 32;
    const int tid = threadIdx.x, tx = tid & 31, ty = tid >> 5;

    for (int r = ty; r < 35; r += 8) {
        int gl = l0 + r - 3;
        sIn[r][tx] = (gl >= 0) ? g_xz[(size_t)(b*LL + gl) * XZW + d0 + tx] : 0.0f;
    }
    __syncthreads();

    float4 w = *(const float4*)(conv_w + (d0 + tx) * 4);
    float cb = conv_b[d0 + tx];
    #pragma unroll
    for (int i = 0; i < 4; ++i) {
        int r = ty + i * 8;
        float v = sIn[r][tx]*w.x + sIn[r+1][tx]*w.y + sIn[r+2][tx]*w.z + sIn[r+3][tx]*w.w + cb;
        v = siluf(v);
        sOut[r][tx] = v;
        size_t idx = (size_t)(b*LL + l0 + r) * DI + d0 + tx;
        __nv_bfloat16 h = __float2bfloat16(v);
        g_xphi[idx] = h;
        g_xplo[idx] = __float2bfloat16(v - __bfloat162float(h));
    }
    __syncthreads();
    #pragma unroll
    for (int i = 0; i < 4; ++i) {
        int dd = ty + i * 8;
        g_xpt[(size_t)(b*DI + d0 + dd) * LL + l0 + tx] = sOut[tx][dd];
    }
}

// ---------------------------------------------------------------------------
// delta transpose + bias + softplus:
// g_dtt[(b*DI+n)*LL + l] = softplus(g_delta[(b*LL+l)*DI + n] + dtb[n])
// ---------------------------------------------------------------------------
__global__ void dtrans_kernel(const float* __restrict__ dtb)
{
    __shared__ float sD[32][33];
    const int b = blockIdx.z, n0 = blockIdx.y * 32, l0 = blockIdx.x * 32;
    const int tid = threadIdx.x, tx = tid & 31, ty = tid >> 5;

    #pragma unroll
    for (int i = 0; i < 4; ++i) {
        int r = ty + i * 8;   // local l
        sD[r][tx] = g_delta[(size_t)(b*LL + l0 + r) * DI + n0 + tx];
    }
    __syncthreads();
    #pragma unroll
    for (int i = 0; i < 4; ++i) {
        int ny = ty + i * 8;  // local n
        int n = n0 + ny;
        float v = softplusf(sD[tx][ny] + dtb[n]);
        g_dtt[(size_t)(b*DI + n) * LL + l0 + tx] = v;
    }
}

// ---------------------------------------------------------------------------
// Chunked selective scan, pass 1: per-chunk final state q_c and sum(dt).
// Thread = (channel, 2 states), 8 lanes per channel. Chunks 0..NCH-2.
// ---------------------------------------------------------------------------
__global__ __launch_bounds__(256)
void scan_pass1(const float* __restrict__ A_log)
{
    const int tid = threadIdx.x;
    const int ch = blockIdx.x * 32 + (tid >> 3);
    const int g  = tid & 7;
    const int c  = blockIdx.y;            // 0..NCH-2
    const int d  = ch & (DI - 1);
    const int b  = ch >> 11;
    const int n0 = g * 2;

    const float A0 = -__expf(A_log[d*DS + n0]);
    const float A1 = -__expf(A_log[d*DS + n0 + 1]);

    const float* __restrict__ dtp = g_dtt + (size_t)ch * LL + c * LC;
    const float* __restrict__ xpp = g_xpt + (size_t)ch * LL + c * LC;
    const float* __restrict__ rp  = g_xdbl + (size_t)(b*LL + c*LC) * XD + DR + n0;

    float h0 = 0.f, h1 = 0.f, sdt = 0.f;
    float dt[2][4], xv[2][4];
    float2 Bv[2][4];

    #pragma unroll
    for (int u = 0; u < 4; ++u) {
        dt[0][u] = __ldg(dtp + u);
        xv[0][u] = __ldg(xpp + u);
        Bv[0][u] = *(const float2*)(rp + (size_t)u * XD);
    }

    for (int l = 0; l < LC; l += 8) {
        #pragma unroll
        for (int u = 0; u < 4; ++u) {
            int ll = l + 4 + u;
            dt[1][u] = __ldg(dtp + ll);
            xv[1][u] = __ldg(xpp + ll);
            Bv[1][u] = *(const float2*)(rp + (size_t)ll * XD);
        }
        #pragma unroll
        for (int u = 0; u < 4; ++u) {
            float dtx = dt[0][u] * xv[0][u];
            h0 = fmaf(__expf(dt[0][u] * A0), h0, dtx * Bv[0][u].x);
            h1 = fmaf(__expf(dt[0][u] * A1), h1, dtx * Bv[0][u].y);
            sdt += dt[0][u];
        }
        int lp = (l + 8 < LC) ? l + 8 : 0;    // clamped prefetch (last unused)
        #pragma unroll
        for (int u = 0; u < 4; ++u) {
            int ll = lp + u;
            dt[0][u] = __ldg(dtp + ll);
            xv[0][u] = __ldg(xpp + ll);
            Bv[0][u] = *(const float2*)(rp + (size_t)ll * XD);
        }
        #pragma unroll
        for (int u = 0; u < 4; ++u) {
            float dtx = dt[1][u] * xv[1][u];
            h0 = fmaf(__expf(dt[1][u] * A0), h0, dtx * Bv[1][u].x);
            h1 = fmaf(__expf(dt[1][u] * A1), h1, dtx * Bv[1][u].y);
            sdt += dt[1][u];
        }
    }

    float* qp = g_q + ((size_t)c * (BB*DI) + ch) * DS + n0;
    qp[0] = h0; qp[1] = h1;
    if (g == 0) g_sdt[(size_t)c * (BB*DI) + ch] = sdt;
}

// ---------------------------------------------------------------------------
// Chunked selective scan, pass 2: carry-in from pass1, full y output.
// ---------------------------------------------------------------------------
__global__ __launch_bounds__(256)
void scan_pass2(const float* __restrict__ A_log, const float* __restrict__ Dv)
{
    const int tid = threadIdx.x;
    const int ch = blockIdx.x * 32 + (tid >> 3);
    const int g  = tid & 7;
    const int c  = blockIdx.y;            // 0..NCH-1
    const int d  = ch & (DI - 1);
    const int b  = ch >> 11;
    const int n0 = g * 2;

    const float A0 = -__expf(A_log[d*DS + n0]);
    const float A1 = -__expf(A_log[d*DS + n0 + 1]);
    const float Dd = Dv[d];

    float h0 = 0.f, h1 = 0.f;
    for (int j = 0; j < c; ++j) {
        float s = __ldg(g_sdt + (size_t)j * (BB*DI) + ch);
        const float* qp = g_q + ((size_t)j * (BB*DI) + ch) * DS + n0;
        h0 = fmaf(__expf(s * A0), h0, __ldg(qp));
        h1 = fmaf(__expf(s * A1), h1, __ldg(qp + 1));
    }

    const float* __restrict__ dtp = g_dtt + (size_t)ch * LL + c * LC;
    const float* __restrict__ xpp = g_xpt + (size_t)ch * LL + c * LC;
    const float* __restrict__ rp  = g_xdbl + (size_t)(b*LL + c*LC) * XD + DR + n0;
    float* __restrict__ yp = g_yt + (size_t)ch * LL + c * LC;

    float dt[2][4], xv[2][4];
    float2 Bv[2][4], Cv[2][4];

    #pragma unroll
    for (int u = 0; u < 4; ++u) {
        dt[0][u] = __ldg(dtp + u);
        xv[0][u] = __ldg(xpp + u);
        Bv[0][u] = *(const float2*)(rp + (size_t)u * XD);
        Cv[0][u] = *(const float2*)(rp + (size_t)u * XD + DS);
    }

    for (int l = 0; l < LC; l += 8) {
        #pragma unroll
        for (int u = 0; u < 4; ++u) {
            int ll = l + 4 + u;
            dt[1][u] = __ldg(dtp + ll);
            xv[1][u] = __ldg(xpp + ll);
            Bv[1][u] = *(const float2*)(rp + (size_t)ll * XD);
            Cv[1][u] = *(const float2*)(rp + (size_t)ll * XD + DS);
        }
        #pragma unroll
        for (int u = 0; u < 4; ++u) {
            float dtx = dt[0][u] * xv[0][u];
            h0 = fmaf(__expf(dt[0][u] * A0), h0, dtx * Bv[0][u].x);
            h1 = fmaf(__expf(dt[0][u] * A1), h1, dtx * Bv[0][u].y);
            float y = fmaf(h0, Cv[0][u].x, h1 * Cv[0][u].y);
            y += __shfl_down_sync(0xffffffffu, y, 4, 8);
            y += __shfl_down_sync(0xffffffffu, y, 2, 8);
            y += __shfl_down_sync(0xffffffffu, y, 1, 8);
            if (g == 0) yp[l + u] = fmaf(Dd, xv[0][u], y);
        }
        int lp = (l + 8 < LC) ? l + 8 : 0;
        #pragma unroll
        for (int u = 0; u < 4; ++u) {
            int ll = lp + u;
            dt[0][u] = __ldg(dtp + ll);
            xv[0][u] = __ldg(xpp + ll);
            Bv[0][u] = *(const float2*)(rp + (size_t)ll * XD);
            Cv[0][u] = *(const float2*)(rp + (size_t)ll * XD + DS);
        }
        #pragma unroll
        for (int u = 0; u < 4; ++u) {
            float dtx = dt[1][u] * xv[1][u];
            h0 = fmaf(__expf(dt[1][u] * A0), h0, dtx * Bv[1][u].x);
            h1 = fmaf(__expf(dt[1][u] * A1), h1, dtx * Bv[1][u].y);
            float y = fmaf(h0, Cv[1][u].x, h1 * Cv[1][u].y);
            y += __shfl_down_sync(0xffffffffu, y, 4, 8);
            y += __shfl_down_sync(0xffffffffu, y, 2, 8);
            y += __shfl_down_sync(0xffffffffu, y, 1, 8);
            if (g == 0) yp[l + 4 + u] = fmaf(Dd, xv[1][u], y);
        }
    }
}

// ---------------------------------------------------------------------------
// g = y_t * silu(z), fused with bf16 hi/lo split (feeds out_proj HMMA)
// ---------------------------------------------------------------------------
__global__ void gmul_split_kernel()
{
    __shared__ float sY[32][33];
    const int b = blockIdx.z, d0 = blockIdx.y * 32, l0 = blockIdx.x * 32;
    const int tid = threadIdx.x, tx = tid & 31, ty = tid >> 5;

    #pragma unroll
    for (int i = 0; i < 4; ++i) {
        int dd = ty + i * 8;
        sY[dd][tx] = g_yt[(size_t)(b*DI + d0 + dd) * LL + l0 + tx];
    }
    __syncthreads();
    #pragma unroll
    for (int i = 0; i < 4; ++i) {
        int r = ty + i * 8;
        size_t idx = (size_t)(b*LL + l0 + r) * DI + d0 + tx;
        float z = g_xz[(size_t)(b*LL + l0 + r) * XZW + DI + d0 + tx];
        float v = sY[tx][r] * siluf(z);
        __nv_bfloat16 h = __float2bfloat16(v);
        g_ghi[idx] = h;
        g_glo[idx] = __float2bfloat16(v - __bfloat162float(h));
    }
}

// ---------------------------------------------------------------------------
extern "C" void kernel_launch(void* const* d_in, const int* in_sizes, int n_in,
                              void* d_out, int out_size)
{
    const float* x       = (const float*)d_in[0];
    const float* in_proj = (const float*)d_in[1];
    const float* conv_w  = (const float*)d_in[2];
    const float* conv_b  = (const float*)d_in[3];
    const float* x_proj  = (const float*)d_in[4];
    const float* dt_w    = (const float*)d_in[5];
    const float* dt_b    = (const float*)d_in[6];
    const float* A_log   = (const float*)d_in[7];
    const float* Dv      = (const float*)d_in[8];
    const float* out_w   = (const float*)d_in[9];
    float* out = (float*)d_out;

    float *xz, *xpart, *delta;
    __nv_bfloat16 *xhi, *xlo, *w1hi, *w1lo, *xphi, *xplo, *w3hi, *w3lo;
    __nv_bfloat16 *dthi, *dtlo, *wdhi, *wdlo, *ghi, *glo, *w2hi, *w2lo;
    cudaGetSymbolAddress((void**)&xz,    g_xz);
    cudaGetSymbolAddress((void**)&xpart, g_xpart);
    cudaGetSymbolAddress((void**)&delta, g_delta);
    cudaGetSymbolAddress((void**)&xhi,   g_xhi);
    cudaGetSymbolAddress((void**)&xlo,   g_xlo);
    cudaGetSymbolAddress((void**)&w1hi,  g_w1hi);
    cudaGetSymbolAddress((void**)&w1lo,  g_w1lo);
    cudaGetSymbolAddress((void**)&xphi,  g_xphi);
    cudaGetSymbolAddress((void**)&xplo,  g_xplo);
    cudaGetSymbolAddress((void**)&w3hi,  g_w3hi);
    cudaGetSymbolAddress((void**)&w3lo,  g_w3lo);
    cudaGetSymbolAddress((void**)&dthi,  g_dthi);
    cudaGetSymbolAddress((void**)&dtlo,  g_dtlo);
    cudaGetSymbolAddress((void**)&wdhi,  g_wdhi);
    cudaGetSymbolAddress((void**)&wdlo,  g_wdlo);
    cudaGetSymbolAddress((void**)&ghi,   g_ghi);
    cudaGetSymbolAddress((void**)&glo,   g_glo);
    cudaGetSymbolAddress((void**)&w2hi,  g_w2hi);
    cudaGetSymbolAddress((void**)&w2lo,  g_w2lo);

    cudaFuncSetAttribute(hmma_gemm, cudaFuncAttributeMaxDynamicSharedMemorySize, HM_SMEM);

    // 0-2) splits (so in_proj hmma sits at launch index 3 for ncu)
    split_bf16<<<(NR*DM/4 + 255)/256, 256>>>(x, xhi, xlo, NR*DM/4);
    split_bf16<<<(XZW*DM/4 + 255)/256, 256>>>(in_proj, w1hi, w1lo, XZW*DM/4);
    split_bf16<<<(DM*DI/4 + 255)/256, 256>>>(out_w, w2hi, w2lo, DM*DI/4);
    // 3) xz = x @ in_proj_w^T  -> [4096, 4096]
    hmma_gemm<<<dim3(XZW/128, NR/128, 1), 256, HM_SMEM>>>(
        xhi, xlo, w1hi, w1lo, xz, XZW, DM, DM, 0);
    // 4) conv + silu (writes bf16 hi/lo + fp32 transposed)
    conv_silu_kernel<<<dim3(LL/32, DI/32, BB), 256>>>(conv_w, conv_b);
    // 5) pad+split x_proj_w; split dt_proj_w
    split_pad_xw<<<(128*DI/4 + 255)/256, 256>>>(x_proj);
    split_bf16<<<(DI*DR/4 + 255)/256, 256>>>(dt_w, wdhi, wdlo, DI*DR/4);
    // 6) x_dbl partials = x_p @ x_proj_w^T (split-K over 8 chunks of 256)
    hmma_gemm<<<dim3(1, NR/128, 8), 256, HM_SMEM>>>(
        xphi, xplo, w3hi, w3lo, xpart, 128, DI, DI/8, (size_t)NR*128);
    // 7) reduce partials -> g_xdbl; also bf16-split delta cols
    reduce_xdbl<<<(NR*24 + 255)/256, 256>>>();
    // 8) delta raw = x_dbl[:, :64] @ dt_proj_w^T (HMMA) -> [4096, 2048]
    hmma_gemm<<<dim3(DI/128, NR/128, 1), 256, HM_SMEM>>>(
        dthi, dtlo, wdhi, wdlo, delta, DI, DR, DR, 0);
    // 9) softplus(delta + bias), transposed to [B,DI,L]
    dtrans_kernel<<<dim3(LL/32, DI/32, BB), 256>>>(dt_b);
    // 10) chunked selective scan (2 passes, 8 chunks of 256)
    scan_pass1<<<dim3((BB*DI)/32, NCH-1), 256>>>(A_log);
    scan_pass2<<<dim3((BB*DI)/32, NCH), 256>>>(A_log, Dv);
    // 11) g = y * silu(z) fused with bf16 split
    gmul_split_kernel<<<dim3(LL/32, DI/32, BB), 256>>>();
    // 12) out = g @ out_proj_w^T
    hmma_gemm<<<dim3(DM/128, NR/128, 1), 256, HM_SMEM>>>(
        ghi, glo, w2hi, w2lo, out, DM, DI, DI, 0);
}